// round 3
// baseline (speedup 1.0000x reference)
#include <cuda_runtime.h>

// Leapfrog (KDK), softened point mass: a = -q / (r*(r+1)^2 + 1e-12).
//
// v3: f32x2-packed pair integration (lo=trail, hi=lead) + ILP=2: each thread
// advances TWO independent pairs (i and i+N/2), interleaving their dependency
// chains to hide MUFU(16cyc)/FMA(4cyc) latency at low warp count.
// Kick denominator shortened: den = fma(r, r2, r) + 2*r2  (= r(r+1)^2 with
// r2 ~= r*r), a 2-FMA chain instead of add->mul->fma.
//
// Inputs: d_in[0]=ts f32[N], d_in[1]=w0_lead f32[N,6], d_in[2]=w0_trail f32[N,6],
//         d_in[3]=n_steps i32. Output f32[2N,6]: row 2i=trail_i, 2i+1=lead_i.

typedef unsigned long long u64;

__device__ __forceinline__ u64 pk2(float lo, float hi) {
    u64 r; asm("mov.b64 %0, {%1, %2};" : "=l"(r) : "f"(lo), "f"(hi)); return r;
}
__device__ __forceinline__ void upk2(u64 v, float& lo, float& hi) {
    asm("mov.b64 {%0, %1}, %2;" : "=f"(lo), "=f"(hi) : "l"(v));
}
__device__ __forceinline__ u64 fma2(u64 a, u64 b, u64 c) {
    u64 d; asm("fma.rn.f32x2 %0, %1, %2, %3;" : "=l"(d) : "l"(a), "l"(b), "l"(c)); return d;
}
__device__ __forceinline__ u64 mul2(u64 a, u64 b) {
    u64 d; asm("mul.rn.f32x2 %0, %1, %2;" : "=l"(d) : "l"(a), "l"(b)); return d;
}
__device__ __forceinline__ float sqrt_ap(float x) {
    float r; asm("sqrt.approx.f32 %0, %1;" : "=f"(r) : "f"(x)); return r;
}
__device__ __forceinline__ float rcp_ap(float x) {
    float r; asm("rcp.approx.f32 %0, %1;" : "=f"(r) : "f"(x)); return r;
}

struct State { u64 qx, qy, qz, px, py, pz; };

// p += coef * accel(q); ncoef2 = packed(-coef) folds the accel sign.
__device__ __forceinline__ void kick(State& s, u64 ncoef2, u64 two2, u64 eps2) {
    u64 r2 = fma2(s.qx, s.qx, fma2(s.qy, s.qy, mul2(s.qz, s.qz)));
    float r2lo, r2hi;  upk2(r2, r2lo, r2hi);
    u64 r  = pk2(sqrt_ap(r2lo), sqrt_ap(r2hi));
    // den = r*(r+1)^2 + eps  ~=  (r*r2 + r) + 2*r2 + eps
    u64 t   = fma2(r, r2, r);          // r*r2 + r
    u64 den = fma2(two2, r2, t);       // + 2*r2
    float dlo, dhi;    upk2(den, dlo, dhi);
    u64 inv = pk2(rcp_ap(dlo), rcp_ap(dhi));
    u64 sc  = mul2(inv, ncoef2);
    s.px = fma2(sc, s.qx, s.px);
    s.py = fma2(sc, s.qy, s.py);
    s.pz = fma2(sc, s.qz, s.pz);
    (void)eps2;
}

__device__ __forceinline__ void drift(State& s, u64 dt2) {
    s.qx = fma2(dt2, s.px, s.qx);
    s.qy = fma2(dt2, s.py, s.qy);
    s.qz = fma2(dt2, s.pz, s.qz);
}

__device__ __forceinline__ void load_state(const float* __restrict__ w0_lead,
                                           const float* __restrict__ w0_trail,
                                           int i, State& s) {
    const float2* __restrict__ rl = reinterpret_cast<const float2*>(w0_lead  + 6 * i);
    const float2* __restrict__ rt = reinterpret_cast<const float2*>(w0_trail + 6 * i);
    float2 l0 = rl[0], l1 = rl[1], l2 = rl[2];
    float2 t0 = rt[0], t1 = rt[1], t2 = rt[2];
    s.qx = pk2(t0.x, l0.x);  s.qy = pk2(t0.y, l0.y);  s.qz = pk2(t1.x, l1.x);
    s.px = pk2(t1.y, l1.y);  s.py = pk2(t2.x, l2.x);  s.pz = pk2(t2.y, l2.y);
}

__device__ __forceinline__ void store_state(float* __restrict__ out, int i, const State& s) {
    float qxt, qxl, qyt, qyl, qzt, qzl, pxt, pxl, pyt, pyl, pzt, pzl;
    upk2(s.qx, qxt, qxl); upk2(s.qy, qyt, qyl); upk2(s.qz, qzt, qzl);
    upk2(s.px, pxt, pxl); upk2(s.py, pyt, pyl); upk2(s.pz, pzt, pzl);
    float4* __restrict__ o = reinterpret_cast<float4*>(out + 12 * i);
    o[0] = make_float4(qxt, qyt, qzt, pxt);
    o[1] = make_float4(pyt, pzt, qxl, qyl);
    o[2] = make_float4(qzl, pxl, pyl, pzl);
}

__global__ void __launch_bounds__(64)
leapfrog_ilp2_kernel(const float* __restrict__ ts,
                     const float* __restrict__ w0_lead,
                     const float* __restrict__ w0_trail,
                     const int*   __restrict__ n_steps_ptr,
                     float* __restrict__ out,
                     int N) {
    int half = N >> 1;
    int i0 = blockIdx.x * blockDim.x + threadIdx.x;
    if (i0 >= half) return;
    int i1 = i0 + half;

    int n_steps = *n_steps_ptr;
    float t_f = ts[N - 1] + 0.001f;
    float inv_ns = 1.0f / (float)n_steps;
    float dt0  = (t_f - ts[i0]) * inv_ns;
    float dt1  = (t_f - ts[i1]) * inv_ns;

    u64 dt2_0  = pk2(dt0, dt0),  ndt2_0 = pk2(-dt0, -dt0),  nh2_0 = pk2(-0.5f * dt0, -0.5f * dt0);
    u64 dt2_1  = pk2(dt1, dt1),  ndt2_1 = pk2(-dt1, -dt1),  nh2_1 = pk2(-0.5f * dt1, -0.5f * dt1);
    u64 two2 = pk2(2.0f, 2.0f);
    u64 eps2 = pk2(1e-12f, 1e-12f);

    State s0, s1;
    load_state(w0_lead, w0_trail, i0, s0);
    load_state(w0_lead, w0_trail, i1, s1);

    // KDK with fused interior kicks; two independent chains interleaved.
    kick(s0, nh2_0, two2, eps2);
    kick(s1, nh2_1, two2, eps2);
    #pragma unroll 4
    for (int it = 0; it < n_steps - 1; ++it) {
        drift(s0, dt2_0);
        drift(s1, dt2_1);
        kick(s0, ndt2_0, two2, eps2);
        kick(s1, ndt2_1, two2, eps2);
    }
    drift(s0, dt2_0);
    drift(s1, dt2_1);
    kick(s0, nh2_0, two2, eps2);
    kick(s1, nh2_1, two2, eps2);

    store_state(out, i0, s0);
    store_state(out, i1, s1);
}

extern "C" void kernel_launch(void* const* d_in, const int* in_sizes, int n_in,
                              void* d_out, int out_size) {
    const float* ts       = (const float*)d_in[0];
    const float* w0_lead  = (const float*)d_in[1];
    const float* w0_trail = (const float*)d_in[2];
    const int*   n_steps  = (const int*)d_in[3];
    float* out = (float*)d_out;

    int N = in_sizes[0];
    int half = N >> 1;
    int threads = 64;
    int blocks = (half + threads - 1) / threads;
    leapfrog_ilp2_kernel<<<blocks, threads>>>(ts, w0_lead, w0_trail, n_steps, out, N);
}

// round 4
// speedup vs baseline: 1.2419x; 1.2419x over previous
#include <cuda_runtime.h>

// Leapfrog (KDK), softened point mass: a = -q / (r*(r+1)^2 + 1e-12).
//
// v4 = R1 launch shape (scalar, 2N threads, max warp count) + R2 algorithmic
// wins:
//  - fused interior kicks (65 accel evals / particle instead of 128)
//  - sqrt.approx / rcp.approx (1 MUFU each, no refinement tail)
//  - den = fma(r, r2, r) + 2*r2  (= r(r+1)^2, 2-FMA chain)
// No f32x2 packing, no ILP: both halve warps, and occupancy is the binding
// resource (R2/R3 evidence).
//
// Inputs: d_in[0]=ts f32[N], d_in[1]=w0_lead f32[N,6], d_in[2]=w0_trail f32[N,6],
//         d_in[3]=n_steps i32. Output f32[2N,6]: row 2i=trail_i, 2i+1=lead_i.

__device__ __forceinline__ float sqrt_ap(float x) {
    float r; asm("sqrt.approx.f32 %0, %1;" : "=f"(r) : "f"(x)); return r;
}
__device__ __forceinline__ float rcp_ap(float x) {
    float r; asm("rcp.approx.f32 %0, %1;" : "=f"(r) : "f"(x)); return r;
}

// p += coef * accel(q); ncoef pre-negated (-coef) to fold accel's sign.
__device__ __forceinline__ void kick(float& qx, float& qy, float& qz,
                                     float& px, float& py, float& pz,
                                     float ncoef) {
    float r2 = fmaf(qx, qx, fmaf(qy, qy, qz * qz));
    float r  = sqrt_ap(r2);
    float t  = fmaf(r, r2, r);          // r*r2 + r
    float den = fmaf(2.0f, r2, t);      // + 2*r2  => r(r+1)^2
    float sc = rcp_ap(den) * ncoef;     // -coef / den
    px = fmaf(sc, qx, px);
    py = fmaf(sc, qy, py);
    pz = fmaf(sc, qz, pz);
}

__global__ void __launch_bounds__(256)
leapfrog_v4_kernel(const float* __restrict__ ts,
                   const float* __restrict__ w0_lead,
                   const float* __restrict__ w0_trail,
                   const int*   __restrict__ n_steps_ptr,
                   float* __restrict__ out,
                   int N) {
    int tid = blockIdx.x * blockDim.x + threadIdx.x;
    if (tid >= 2 * N) return;

    int b = (tid >= N) ? 1 : 0;        // 0 = trail, 1 = lead
    int i = tid - b * N;

    const float* __restrict__ w0 = b ? w0_lead : w0_trail;

    int n_steps = *n_steps_ptr;
    float t_f = ts[N - 1] + 0.001f;    // broadcast, L2-resident
    float dt  = (t_f - ts[i]) / (float)n_steps;
    float nhdt = -0.5f * dt;
    float ndt  = -dt;

    const float2* __restrict__ row = reinterpret_cast<const float2*>(w0 + 6 * i);
    float2 v0 = row[0];
    float2 v1 = row[1];
    float2 v2 = row[2];
    float qx = v0.x, qy = v0.y, qz = v1.x;
    float px = v1.y, py = v2.x, pz = v2.y;

    // KDK with fused interior kicks:
    //   half kick; (n-1) x (drift; full kick); drift; half kick.
    kick(qx, qy, qz, px, py, pz, nhdt);
    #pragma unroll 4
    for (int s = 0; s < n_steps - 1; ++s) {
        qx = fmaf(dt, px, qx);
        qy = fmaf(dt, py, qy);
        qz = fmaf(dt, pz, qz);
        kick(qx, qy, qz, px, py, pz, ndt);
    }
    qx = fmaf(dt, px, qx);
    qy = fmaf(dt, py, qy);
    qz = fmaf(dt, pz, qz);
    kick(qx, qy, qz, px, py, pz, nhdt);

    int orow = 2 * i + b;
    float2* __restrict__ orow_p = reinterpret_cast<float2*>(out + 6 * orow);
    orow_p[0] = make_float2(qx, qy);
    orow_p[1] = make_float2(qz, px);
    orow_p[2] = make_float2(py, pz);
}

extern "C" void kernel_launch(void* const* d_in, const int* in_sizes, int n_in,
                              void* d_out, int out_size) {
    const float* ts       = (const float*)d_in[0];
    const float* w0_lead  = (const float*)d_in[1];
    const float* w0_trail = (const float*)d_in[2];
    const int*   n_steps  = (const int*)d_in[3];
    float* out = (float*)d_out;

    int N = in_sizes[0];
    int total = 2 * N;
    int threads = 256;
    int blocks = (total + threads - 1) / threads;
    leapfrog_v4_kernel<<<blocks, threads>>>(ts, w0_lead, w0_trail, n_steps, out, N);
}